// round 6
// baseline (speedup 1.0000x reference)
#include <cuda_runtime.h>
#include <cuda_bf16.h>

// Problem constants
#define BB   512
#define LL   16384
#define NW   (LL - 5 + 1)          // 16380 windows

// Tiling
#define TPB  128                   // 4 warps
#define SEGW 128                   // windows (=elements) per warp
#define CW   512                   // windows per block
#define NWCH (LL / CW)             // 32 window chunks
#define BC   8                     // batches per block
#define NBCH (BB / BC)             // 64 batch chunks
#define NWG  (LL / SEGW)           // 128 warp-groups along L
#define NBLK (NWCH * NBCH)         // 2048 blocks
#define NVW  (NWG * 4)             // 512 validity words (1 bit per window)

// Deterministic scratch (no cudaMalloc allowed).
__device__ float        g_sq_blk[NBLK];   // one sq partial per block (8 KB)
__device__ unsigned     g_vld_or[NVW];    // OR-accumulated validity (2 KB);
                                          // zeroed by last block each launch
__device__ unsigned int g_done;           // arrival counter; atomicInc wraps
                                          // at NBLK-1 -> self-resets per launch

__device__ __forceinline__ float sigm(float x0, float x1) {
    // softmax(x)[...,1] == sigmoid(x1-x0) == 1/(1+exp(x0-x1))
    return __fdividef(1.0f, 1.0f + __expf(x0 - x1));
}

// Per-window math. smm = packed sliding sum (msum + 32*tsum), spm = sum(p*m),
// sq = sum(p^2*m). msum integer-valued => pvar = sq/denom - pmean^2,
// tvar = tmean*(1-tmean). Matches reference up to f32 rounding.
#define WIN(K, ACC) { \
    float stm   = floorf(smm * 0.03125f); \
    float sm    = fmaf(-32.0f, stm, smm); \
    float denom = fmaxf(sm, 1.0f); \
    float rd    = __fdividef(1.0f, denom); \
    float pmean = spm * rd; \
    float tmean = stm * rd; \
    float pvar  = fmaf(-pmean, pmean, sq * rd); \
    float tvar  = fmaf(-tmean, tmean, tmean); \
    float d     = pvar - tvar; \
    ACC = fmaf(d, d, ACC); \
    if (sm > 0.0f) vmask |= (1u << (K)); \
}

__global__ __launch_bounds__(TPB, 8)
void bcl_fused(const float* __restrict__ pred,
               const int*   __restrict__ tgt,
               const int*   __restrict__ msk,
               float*       __restrict__ out)
{
    const int lane = threadIdx.x & 31;
    const int wrp  = threadIdx.x >> 5;
    const int seg  = blockIdx.x * CW + wrp * SEGW;  // warp's first element/window
    const int bch  = blockIdx.y;
    const bool has_halo = (seg + SEGW) < LL;        // next 4 elems exist?
    const int hofs = has_halo ? (SEGW / 4) : 0;     // int4/2xfloat4 halo offset
    const int w    = seg + 4 * lane;                // lane's first window

    float acc0 = 0.f, acc1 = 0.f, acc2 = 0.f, acc3 = 0.f;
    unsigned vmask = 0u;

    for (int bi = 0; bi < BC; bi++) {
        const int b = bch * BC + bi;
        const size_t eb = (size_t)b * LL + seg;
        const float4* fp4 = (const float4*)(pred + 2 * eb);
        const int4*   t4p = (const int4*)(tgt + eb);
        const int4*   m4p = (const int4*)(msk + eb);

        // Own loads: lane owns elems seg+4*lane .. +3 (32B/16B lane stride)
        float4 v0 = fp4[2 * lane];
        float4 v1 = fp4[2 * lane + 1];
        int4   tv = t4p[lane];
        int4   mv = m4p[lane];
        // Halo loads (broadcast address; used only by lane 31)
        float4 h0 = fp4[2 * hofs];
        float4 h1 = fp4[2 * hofs + 1];
        int4   htv = t4p[hofs];
        int4   hmv = m4p[hofs];
        if (!has_halo) { hmv.x = 0; hmv.y = 0; hmv.z = 0; hmv.w = 0; }

        // Derived per-element: mm = m + 32*(t&m); pm = p*m; q = p^2*m
        float p0 = sigm(v0.x, v0.y), p1 = sigm(v0.z, v0.w);
        float p2 = sigm(v1.x, v1.y), p3 = sigm(v1.z, v1.w);
        float mm0 = (float)(mv.x + ((tv.x & mv.x) << 5));
        float mm1 = (float)(mv.y + ((tv.y & mv.y) << 5));
        float mm2 = (float)(mv.z + ((tv.z & mv.z) << 5));
        float mm3 = (float)(mv.w + ((tv.w & mv.w) << 5));
        float pm0 = mv.x ? p0 : 0.f, pm1 = mv.y ? p1 : 0.f;
        float pm2 = mv.z ? p2 : 0.f, pm3 = mv.w ? p3 : 0.f;
        float q0 = p0 * pm0, q1 = p1 * pm1, q2 = p2 * pm2, q3 = p3 * pm3;

        // Neighbor (lane+1) quantities via shfl; convergent, before any branch.
        float nmm0 = __shfl_down_sync(0xffffffffu, mm0, 1);
        float nmm1 = __shfl_down_sync(0xffffffffu, mm1, 1);
        float nmm2 = __shfl_down_sync(0xffffffffu, mm2, 1);
        float nmm3 = __shfl_down_sync(0xffffffffu, mm3, 1);
        float npm0 = __shfl_down_sync(0xffffffffu, pm0, 1);
        float npm1 = __shfl_down_sync(0xffffffffu, pm1, 1);
        float npm2 = __shfl_down_sync(0xffffffffu, pm2, 1);
        float npm3 = __shfl_down_sync(0xffffffffu, pm3, 1);
        float nq0  = __shfl_down_sync(0xffffffffu, q0, 1);
        float nq1  = __shfl_down_sync(0xffffffffu, q1, 1);
        float nq2  = __shfl_down_sync(0xffffffffu, q2, 1);
        float nq3  = __shfl_down_sync(0xffffffffu, q3, 1);

        if (lane == 31) {
            // Patch halo from broadcast loads (mask-gated zeros if no halo).
            float hp0 = sigm(h0.x, h0.y), hp1 = sigm(h0.z, h0.w);
            float hp2 = sigm(h1.x, h1.y), hp3 = sigm(h1.z, h1.w);
            nmm0 = (float)(hmv.x + ((htv.x & hmv.x) << 5));
            nmm1 = (float)(hmv.y + ((htv.y & hmv.y) << 5));
            nmm2 = (float)(hmv.z + ((htv.z & hmv.z) << 5));
            nmm3 = (float)(hmv.w + ((htv.w & hmv.w) << 5));
            npm0 = hmv.x ? hp0 : 0.f; npm1 = hmv.y ? hp1 : 0.f;
            npm2 = hmv.z ? hp2 : 0.f; npm3 = hmv.w ? hp3 : 0.f;
            nq0 = hp0 * npm0; nq1 = hp1 * npm1; nq2 = hp2 * npm2; nq3 = hp3 * npm3;
        }

        // Sliding window-5 sums over {own0..3, n0..3}, incremental.
        float smm = mm0 + mm1 + mm2 + mm3 + nmm0;
        float spm = pm0 + pm1 + pm2 + pm3 + npm0;
        float sq  = q0 + q1 + q2 + q3 + nq0;
        WIN(0, acc0)
        smm += nmm1 - mm0; spm += npm1 - pm0; sq += nq1 - q0;
        WIN(1, acc1)
        smm += nmm2 - mm1; spm += npm2 - pm1; sq += nq2 - q1;
        WIN(2, acc2)
        smm += nmm3 - mm2; spm += npm3 - pm2; sq += nq3 - q2;
        WIN(3, acc3)
    }

    // Gate off windows >= NW — they read OOB-zeroed halo and must be
    // excluded from both sq and validity.
    unsigned amask = 0u;
    if (w + 0 < NW) amask |= 1u; else acc0 = 0.f;
    if (w + 1 < NW) amask |= 2u; else acc1 = 0.f;
    if (w + 2 < NW) amask |= 4u; else acc2 = 0.f;
    if (w + 3 < NW) amask |= 8u; else acc3 = 0.f;
    vmask &= amask;

    // Validity: ballot-pack, OR into global per-window bit array.
    // Integer atomicOr is order-independent -> deterministic.
    unsigned b0 = __ballot_sync(0xffffffffu, (vmask >> 0) & 1u);
    unsigned b1 = __ballot_sync(0xffffffffu, (vmask >> 1) & 1u);
    unsigned b2 = __ballot_sync(0xffffffffu, (vmask >> 2) & 1u);
    unsigned b3 = __ballot_sync(0xffffffffu, (vmask >> 3) & 1u);
    if (lane == 0) {
        const int wg = seg / SEGW;
        atomicOr(&g_vld_or[wg * 4 + 0], b0);
        atomicOr(&g_vld_or[wg * 4 + 1], b1);
        atomicOr(&g_vld_or[wg * 4 + 2], b2);
        atomicOr(&g_vld_or[wg * 4 + 3], b3);
        __threadfence();   // make this warp's ORs globally visible
    }

    // In-block deterministic reduction of sq -> one float per block.
    float a = (acc0 + acc1) + (acc2 + acc3);
    a += __shfl_xor_sync(0xffffffffu, a, 16);
    a += __shfl_xor_sync(0xffffffffu, a, 8);
    a += __shfl_xor_sync(0xffffffffu, a, 4);
    a += __shfl_xor_sync(0xffffffffu, a, 2);
    a += __shfl_xor_sync(0xffffffffu, a, 1);
    __shared__ float s_red[4];
    __shared__ unsigned s_last;
    if (lane == 0) s_red[wrp] = a;
    __syncthreads();
    if (threadIdx.x == 0) {
        g_sq_blk[bch * NWCH + blockIdx.x] =
            (s_red[0] + s_red[1]) + (s_red[2] + s_red[3]);
        __threadfence();   // partial visible before arrival
        // Wrapping arrival counter: self-resets to 0 after NBLK increments.
        unsigned old = atomicInc(&g_done, NBLK - 1);
        s_last = (old == NBLK - 1) ? 1u : 0u;
    }
    __syncthreads();
    if (!s_last) return;

    // ---- Last block: final reduction (8 KB sq + 2 KB validity) ----
    __threadfence();       // acquire: all other blocks' fenced writes visible
    const int t = threadIdx.x;

    float s = 0.f;
    const float4* sq4 = (const float4*)g_sq_blk;
#pragma unroll
    for (int i = 0; i < 4; i++) {
        float4 v = sq4[t + 128 * i];
        s += (v.x + v.y) + (v.z + v.w);
    }
    uint4 vv = ((const uint4*)g_vld_or)[t];   // 512 words / 128 thr
    int c = __popc(vv.x) + __popc(vv.y) + __popc(vv.z) + __popc(vv.w);
    // Zero validity accumulator for the next graph replay.
    ((uint4*)g_vld_or)[t] = make_uint4(0u, 0u, 0u, 0u);

    // Block reduce s and c.
    s += __shfl_xor_sync(0xffffffffu, s, 16);
    s += __shfl_xor_sync(0xffffffffu, s, 8);
    s += __shfl_xor_sync(0xffffffffu, s, 4);
    s += __shfl_xor_sync(0xffffffffu, s, 2);
    s += __shfl_xor_sync(0xffffffffu, s, 1);
    c += __shfl_xor_sync(0xffffffffu, c, 16);
    c += __shfl_xor_sync(0xffffffffu, c, 8);
    c += __shfl_xor_sync(0xffffffffu, c, 4);
    c += __shfl_xor_sync(0xffffffffu, c, 2);
    c += __shfl_xor_sync(0xffffffffu, c, 1);
    __shared__ float fs[4];
    __shared__ int   fc[4];
    if (lane == 0) { fs[wrp] = s; fc[wrp] = c; }
    __syncthreads();
    if (t == 0) {
        float S = (fs[0] + fs[1]) + (fs[2] + fs[3]);
        int   C = (fc[0] + fc[1]) + (fc[2] + fc[3]);
        out[0] = S * (1.0f / (float)BB) / fmaxf((float)C, 1.0f);
    }
}

extern "C" void kernel_launch(void* const* d_in, const int* in_sizes, int n_in,
                              void* d_out, int out_size)
{
    const float* pred = (const float*)d_in[0];   // [512, 16384, 2] f32
    const int*   tgt  = (const int*)d_in[1];     // [512, 16384] i32
    const int*   msk  = (const int*)d_in[2];     // [512, 16384] i32

    dim3 grid(NWCH, NBCH);                        // 32 x 64 = 2048 blocks
    bcl_fused<<<grid, TPB>>>(pred, tgt, msk, (float*)d_out);
}

// round 7
// speedup vs baseline: 1.1220x; 1.1220x over previous
#include <cuda_runtime.h>
#include <cuda_bf16.h>

// Problem constants
#define BB   512
#define LL   16384
#define NW   (LL - 5 + 1)          // 16380 windows

// Tiling
#define TPB  128                   // 4 warps
#define SEGW 128                   // windows (=elements) per warp
#define CW   512                   // windows per block
#define NWCH (LL / CW)             // 32 window chunks
#define BC   16                    // batches per block
#define NBCH (BB / BC)             // 32 batch chunks
#define NWG  (LL / SEGW)           // 128 warp-groups along L
#define NBLK (NWCH * NBCH)         // 1024 blocks -> single wave @ 7/SM
#define NVW  (NWG * 4)             // 512 validity words (1 bit per window)

// Deterministic scratch (no cudaMalloc allowed).
__device__ float        g_sq_blk[NBLK];   // one sq partial per block (4 KB)
__device__ unsigned     g_vld_or[NVW];    // OR-accumulated validity (2 KB);
                                          // zeroed by last block each launch
__device__ unsigned int g_done;           // arrival counter; atomicInc wraps
                                          // at NBLK-1 -> self-resets per launch

__device__ __forceinline__ float sigm(float x0, float x1) {
    // softmax(x)[...,1] == sigmoid(x1-x0) == 1/(1+exp(x0-x1))
    return __fdividef(1.0f, 1.0f + __expf(x0 - x1));
}

// Per-window math. smm = packed sliding sum (msum + 32*tsum), spm = sum(p*m),
// sq = sum(p^2*m). msum integer-valued => pvar = sq/denom - pmean^2,
// tvar = tmean*(1-tmean). Matches reference up to f32 rounding.
#define WIN(K, ACC) { \
    float stm   = floorf(smm * 0.03125f); \
    float sm    = fmaf(-32.0f, stm, smm); \
    float denom = fmaxf(sm, 1.0f); \
    float rd    = __fdividef(1.0f, denom); \
    float pmean = spm * rd; \
    float tmean = stm * rd; \
    float pvar  = fmaf(-pmean, pmean, sq * rd); \
    float tvar  = fmaf(-tmean, tmean, tmean); \
    float d     = pvar - tvar; \
    ACC = fmaf(d, d, ACC); \
    if (sm > 0.0f) vmask |= (1u << (K)); \
}

__global__ __launch_bounds__(TPB, 7)
void bcl_fused(const float* __restrict__ pred,
               const int*   __restrict__ tgt,
               const int*   __restrict__ msk,
               float*       __restrict__ out)
{
    const int lane = threadIdx.x & 31;
    const int wrp  = threadIdx.x >> 5;
    const int seg  = blockIdx.x * CW + wrp * SEGW;  // warp's first element/window
    const int bch  = blockIdx.y;
    const bool has_halo = (seg + SEGW) < LL;        // next 4 elems exist?
    const int hofs = has_halo ? (SEGW / 4) : 0;     // int4/2xfloat4 halo offset
    const int w    = seg + 4 * lane;                // lane's first window

    float acc0 = 0.f, acc1 = 0.f, acc2 = 0.f, acc3 = 0.f;
    unsigned vmask = 0u;

    const size_t eb0 = (size_t)(bch * BC) * LL + seg;
    const float4* fp4 = (const float4*)(pred + 2 * eb0);
    const int4*   t4p = (const int4*)(tgt + eb0);
    const int4*   m4p = (const int4*)(msk + eb0);

    // Pipeline prologue: preload first iter's pred vectors.
    float4 v0 = fp4[2 * lane];
    float4 v1 = fp4[2 * lane + 1];

    for (int bi = 0; bi < BC; bi++) {
        // Issue this iter's remaining loads up front...
        int4   tv  = t4p[lane];
        int4   mv  = m4p[lane];
        float4 h0  = fp4[2 * hofs];
        float4 h1  = fp4[2 * hofs + 1];
        int4   htv = t4p[hofs];
        int4   hmv = m4p[hofs];
        // ...and prefetch NEXT iter's pred (guarded: reload current on last).
        const float4* fp4n = fp4 + (LL / 2);
        const float4* pf   = (bi < BC - 1) ? fp4n : fp4;
        float4 nx0 = pf[2 * lane];
        float4 nx1 = pf[2 * lane + 1];

        if (!has_halo) { hmv.x = 0; hmv.y = 0; hmv.z = 0; hmv.w = 0; }

        // Own derived: p = sigmoid; mm = m + 32*(t&m); pm = p*m; q = p^2*m
        float p0 = sigm(v0.x, v0.y), p1 = sigm(v0.z, v0.w);
        float p2 = sigm(v1.x, v1.y), p3 = sigm(v1.z, v1.w);
        float mm0 = (float)(mv.x + ((tv.x & mv.x) << 5));
        float mm1 = (float)(mv.y + ((tv.y & mv.y) << 5));
        float mm2 = (float)(mv.z + ((tv.z & mv.z) << 5));
        float mm3 = (float)(mv.w + ((tv.w & mv.w) << 5));
        float pm0 = mv.x ? p0 : 0.f, pm1 = mv.y ? p1 : 0.f;
        float pm2 = mv.z ? p2 : 0.f, pm3 = mv.w ? p3 : 0.f;
        float q0 = p0 * pm0, q1 = p1 * pm1, q2 = p2 * pm2, q3 = p3 * pm3;

        // Halo derived, computed uniformly (frees raw halo regs early;
        // only lane 31 consumes these).
        float hp0 = sigm(h0.x, h0.y), hp1 = sigm(h0.z, h0.w);
        float hp2 = sigm(h1.x, h1.y), hp3 = sigm(h1.z, h1.w);
        float hmm0 = (float)(hmv.x + ((htv.x & hmv.x) << 5));
        float hmm1 = (float)(hmv.y + ((htv.y & hmv.y) << 5));
        float hmm2 = (float)(hmv.z + ((htv.z & hmv.z) << 5));
        float hmm3 = (float)(hmv.w + ((htv.w & hmv.w) << 5));
        float hpm0 = hmv.x ? hp0 : 0.f, hpm1 = hmv.y ? hp1 : 0.f;
        float hpm2 = hmv.z ? hp2 : 0.f, hpm3 = hmv.w ? hp3 : 0.f;
        float hq0 = hp0 * hpm0, hq1 = hp1 * hpm1;
        float hq2 = hp2 * hpm2, hq3 = hp3 * hpm3;

        // Neighbor (lane+1) quantities via shfl; convergent.
        float nmm0 = __shfl_down_sync(0xffffffffu, mm0, 1);
        float nmm1 = __shfl_down_sync(0xffffffffu, mm1, 1);
        float nmm2 = __shfl_down_sync(0xffffffffu, mm2, 1);
        float nmm3 = __shfl_down_sync(0xffffffffu, mm3, 1);
        float npm0 = __shfl_down_sync(0xffffffffu, pm0, 1);
        float npm1 = __shfl_down_sync(0xffffffffu, pm1, 1);
        float npm2 = __shfl_down_sync(0xffffffffu, pm2, 1);
        float npm3 = __shfl_down_sync(0xffffffffu, pm3, 1);
        float nq0  = __shfl_down_sync(0xffffffffu, q0, 1);
        float nq1  = __shfl_down_sync(0xffffffffu, q1, 1);
        float nq2  = __shfl_down_sync(0xffffffffu, q2, 1);
        float nq3  = __shfl_down_sync(0xffffffffu, q3, 1);

        // Lane 31 takes the precomputed halo values (predicated moves).
        if (lane == 31) {
            nmm0 = hmm0; nmm1 = hmm1; nmm2 = hmm2; nmm3 = hmm3;
            npm0 = hpm0; npm1 = hpm1; npm2 = hpm2; npm3 = hpm3;
            nq0  = hq0;  nq1  = hq1;  nq2  = hq2;  nq3  = hq3;
        }

        // Sliding window-5 sums over {own0..3, n0..3}, incremental.
        float smm = mm0 + mm1 + mm2 + mm3 + nmm0;
        float spm = pm0 + pm1 + pm2 + pm3 + npm0;
        float sq  = q0 + q1 + q2 + q3 + nq0;
        WIN(0, acc0)
        smm += nmm1 - mm0; spm += npm1 - pm0; sq += nq1 - q0;
        WIN(1, acc1)
        smm += nmm2 - mm1; spm += npm2 - pm1; sq += nq2 - q1;
        WIN(2, acc2)
        smm += nmm3 - mm2; spm += npm3 - pm2; sq += nq3 - q2;
        WIN(3, acc3)

        // Rotate pipeline.
        v0 = nx0; v1 = nx1;
        fp4 = fp4n; t4p += (LL / 4); m4p += (LL / 4);
    }

    // Gate off windows >= NW — they read OOB-zeroed halo and must be
    // excluded from both sq and validity.
    unsigned amask = 0u;
    if (w + 0 < NW) amask |= 1u; else acc0 = 0.f;
    if (w + 1 < NW) amask |= 2u; else acc1 = 0.f;
    if (w + 2 < NW) amask |= 4u; else acc2 = 0.f;
    if (w + 3 < NW) amask |= 8u; else acc3 = 0.f;
    vmask &= amask;

    // Validity: ballot-pack, OR into global per-window bit array.
    // Integer atomicOr is order-independent -> deterministic.
    unsigned b0 = __ballot_sync(0xffffffffu, (vmask >> 0) & 1u);
    unsigned b1 = __ballot_sync(0xffffffffu, (vmask >> 1) & 1u);
    unsigned b2 = __ballot_sync(0xffffffffu, (vmask >> 2) & 1u);
    unsigned b3 = __ballot_sync(0xffffffffu, (vmask >> 3) & 1u);
    if (lane == 0) {
        const int wg = seg / SEGW;
        atomicOr(&g_vld_or[wg * 4 + 0], b0);
        atomicOr(&g_vld_or[wg * 4 + 1], b1);
        atomicOr(&g_vld_or[wg * 4 + 2], b2);
        atomicOr(&g_vld_or[wg * 4 + 3], b3);
        __threadfence();   // make this warp's ORs globally visible
    }

    // In-block deterministic reduction of sq -> one float per block.
    float a = (acc0 + acc1) + (acc2 + acc3);
    a += __shfl_xor_sync(0xffffffffu, a, 16);
    a += __shfl_xor_sync(0xffffffffu, a, 8);
    a += __shfl_xor_sync(0xffffffffu, a, 4);
    a += __shfl_xor_sync(0xffffffffu, a, 2);
    a += __shfl_xor_sync(0xffffffffu, a, 1);
    __shared__ float s_red[4];
    __shared__ unsigned s_last;
    if (lane == 0) s_red[wrp] = a;
    __syncthreads();
    if (threadIdx.x == 0) {
        g_sq_blk[bch * NWCH + blockIdx.x] =
            (s_red[0] + s_red[1]) + (s_red[2] + s_red[3]);
        __threadfence();   // partial visible before arrival
        // Wrapping arrival counter: self-resets to 0 after NBLK increments.
        unsigned old = atomicInc(&g_done, NBLK - 1);
        s_last = (old == NBLK - 1) ? 1u : 0u;
    }
    __syncthreads();
    if (!s_last) return;

    // ---- Last block: final reduction (4 KB sq + 2 KB validity) ----
    __threadfence();       // acquire: all other blocks' fenced writes visible
    const int t = threadIdx.x;

    float s = 0.f;
    const float4* sq4 = (const float4*)g_sq_blk;   // 1024 floats = 256 float4
#pragma unroll
    for (int i = 0; i < 2; i++) {
        float4 v = sq4[t + 128 * i];
        s += (v.x + v.y) + (v.z + v.w);
    }
    uint4 vv = ((const uint4*)g_vld_or)[t];        // 512 words / 128 thr
    int c = __popc(vv.x) + __popc(vv.y) + __popc(vv.z) + __popc(vv.w);
    // Zero validity accumulator for the next graph replay.
    ((uint4*)g_vld_or)[t] = make_uint4(0u, 0u, 0u, 0u);

    // Block reduce s and c.
    s += __shfl_xor_sync(0xffffffffu, s, 16);
    s += __shfl_xor_sync(0xffffffffu, s, 8);
    s += __shfl_xor_sync(0xffffffffu, s, 4);
    s += __shfl_xor_sync(0xffffffffu, s, 2);
    s += __shfl_xor_sync(0xffffffffu, s, 1);
    c += __shfl_xor_sync(0xffffffffu, c, 16);
    c += __shfl_xor_sync(0xffffffffu, c, 8);
    c += __shfl_xor_sync(0xffffffffu, c, 4);
    c += __shfl_xor_sync(0xffffffffu, c, 2);
    c += __shfl_xor_sync(0xffffffffu, c, 1);
    __shared__ float fs[4];
    __shared__ int   fc[4];
    if (lane == 0) { fs[wrp] = s; fc[wrp] = c; }
    __syncthreads();
    if (t == 0) {
        float S = (fs[0] + fs[1]) + (fs[2] + fs[3]);
        int   C = (fc[0] + fc[1]) + (fc[2] + fc[3]);
        out[0] = S * (1.0f / (float)BB) / fmaxf((float)C, 1.0f);
    }
}

extern "C" void kernel_launch(void* const* d_in, const int* in_sizes, int n_in,
                              void* d_out, int out_size)
{
    const float* pred = (const float*)d_in[0];   // [512, 16384, 2] f32
    const int*   tgt  = (const int*)d_in[1];     // [512, 16384] i32
    const int*   msk  = (const int*)d_in[2];     // [512, 16384] i32

    dim3 grid(NWCH, NBCH);                        // 32 x 32 = 1024 blocks
    bcl_fused<<<grid, TPB>>>(pred, tgt, msk, (float*)d_out);
}

// round 8
// speedup vs baseline: 1.1311x; 1.0082x over previous
#include <cuda_runtime.h>
#include <cuda_bf16.h>

// Problem constants
#define BB   512
#define LL   16384
#define NW   (LL - 5 + 1)          // 16380 windows

// Tiling
#define TPB  128                   // 4 warps
#define SEGW 128                   // windows (=elements) per warp
#define CW   512                   // windows per block
#define NWCH (LL / CW)             // 32 window chunks
#define BC   16                    // batches per block
#define NBCH (BB / BC)             // 32 batch chunks
#define NWG  (LL / SEGW)           // 128 warp-groups along L
#define NBLK (NWCH * NBCH)         // 1024 blocks -> single wave
#define NVW  (NWG * 4)             // 512 validity words (1 bit per window)

// Deterministic scratch (no cudaMalloc allowed).
__device__ float        g_sq_blk[NBLK];   // one sq partial per block (4 KB)
__device__ unsigned     g_vld_or[NVW];    // OR-accumulated validity (2 KB);
                                          // zeroed by last block each launch
__device__ unsigned int g_done;           // arrival counter; atomicInc wraps
                                          // at NBLK-1 -> self-resets per launch

__device__ __forceinline__ float sigm(float x0, float x1) {
    // softmax(x)[...,1] == sigmoid(x1-x0) == 1/(1+exp(x0-x1))
    return __fdividef(1.0f, 1.0f + __expf(x0 - x1));
}

// Per-window math. smm = packed sliding sum (msum + 32*tsum), spm = sum(p*m),
// sq = sum(p^2*m). msum integer-valued => pvar = sq/denom - pmean^2,
// tvar = tmean*(1-tmean). Matches reference up to f32 rounding.
#define WIN(K, ACC) { \
    float stm   = floorf(smm * 0.03125f); \
    float sm    = fmaf(-32.0f, stm, smm); \
    float denom = fmaxf(sm, 1.0f); \
    float rd    = __fdividef(1.0f, denom); \
    float pmean = spm * rd; \
    float tmean = stm * rd; \
    float pvar  = fmaf(-pmean, pmean, sq * rd); \
    float tvar  = fmaf(-tmean, tmean, tmean); \
    float d     = pvar - tvar; \
    ACC = fmaf(d, d, ACC); \
    if (sm > 0.0f) vmask |= (1u << (K)); \
}

__global__ __launch_bounds__(TPB, 8)
void bcl_fused(const float* __restrict__ pred,
               const int*   __restrict__ tgt,
               const int*   __restrict__ msk,
               float*       __restrict__ out)
{
    const int lane = threadIdx.x & 31;
    const int wrp  = threadIdx.x >> 5;
    const int seg  = blockIdx.x * CW + wrp * SEGW;  // warp's first element/window
    const int bch  = blockIdx.y;
    const int w    = seg + 4 * lane;                // lane's first window
    const bool blk_halo = (blockIdx.x < NWCH - 1);  // block-edge halo exists?

    // Boundary exchange buffers: [double-buffer][slot 0..3][12 floats]
    // slot w-1 <- warp w lane 0's derived values (w=1..3)
    // slot 3   <- block-edge halo (computed by warp 0 lanes 0..3 from gmem)
    __shared__ float xbuf[2][4][12];
    __shared__ float s_red[4];
    __shared__ unsigned s_last;

    float acc0 = 0.f, acc1 = 0.f, acc2 = 0.f, acc3 = 0.f;
    unsigned vmask = 0u;

    const size_t eb0 = (size_t)(bch * BC) * LL + seg;
    const float4* fp4 = (const float4*)(pred + 2 * eb0);
    const int4*   t4p = (const int4*)(tgt + eb0);
    const int4*   m4p = (const int4*)(msk + eb0);

    for (int bi = 0; bi < BC; bi++) {
        const int buf = bi & 1;
        // Own loads: lane owns 4 consecutive elems (32B/16B lane stride).
        float4 v0 = fp4[2 * lane];
        float4 v1 = fp4[2 * lane + 1];
        int4   tv = t4p[lane];
        int4   mv = m4p[lane];

        // Own derived: p = sigmoid; mm = m + 32*(t&m); pm = p*m; q = p^2*m
        float p0 = sigm(v0.x, v0.y), p1 = sigm(v0.z, v0.w);
        float p2 = sigm(v1.x, v1.y), p3 = sigm(v1.z, v1.w);
        float mm0 = (float)(mv.x + ((tv.x & mv.x) << 5));
        float mm1 = (float)(mv.y + ((tv.y & mv.y) << 5));
        float mm2 = (float)(mv.z + ((tv.z & mv.z) << 5));
        float mm3 = (float)(mv.w + ((tv.w & mv.w) << 5));
        float pm0 = mv.x ? p0 : 0.f, pm1 = mv.y ? p1 : 0.f;
        float pm2 = mv.z ? p2 : 0.f, pm3 = mv.w ? p3 : 0.f;
        float q0 = p0 * pm0, q1 = p1 * pm1, q2 = p2 * pm2, q3 = p3 * pm3;

        // Publish boundary values.
        if (wrp == 0) {
            if (lane < 4) {
                // Block-edge halo: element (block_base + 512 + lane).
                // Warp 0's pointers are at block base, so offset is 512+lane.
                const float* prf = (const float*)fp4;
                const int*   trf = (const int*)t4p;
                const int*   mrf = (const int*)m4p;
                int off = blk_halo ? (4 * SEGW + lane) : 0;
                float a0 = prf[2 * off], a1 = prf[2 * off + 1];
                int ht = trf[off], hm = mrf[off];
                if (!blk_halo) { ht = 0; hm = 0; }
                float hp  = sigm(a0, a1);
                float hpm = hm ? hp : 0.f;
                xbuf[buf][3][lane]     = (float)(hm + ((ht & hm) << 5));
                xbuf[buf][3][4 + lane] = hpm;
                xbuf[buf][3][8 + lane] = hp * hpm;
            }
        } else if (lane == 0) {
            float4* xs = (float4*)xbuf[buf][wrp - 1];
            xs[0] = make_float4(mm0, mm1, mm2, mm3);
            xs[1] = make_float4(pm0, pm1, pm2, pm3);
            xs[2] = make_float4(q0, q1, q2, q3);
        }
        __syncthreads();

        // Neighbor (lane+1) quantities via shfl; convergent.
        float nmm0 = __shfl_down_sync(0xffffffffu, mm0, 1);
        float nmm1 = __shfl_down_sync(0xffffffffu, mm1, 1);
        float nmm2 = __shfl_down_sync(0xffffffffu, mm2, 1);
        float nmm3 = __shfl_down_sync(0xffffffffu, mm3, 1);
        float npm0 = __shfl_down_sync(0xffffffffu, pm0, 1);
        float npm1 = __shfl_down_sync(0xffffffffu, pm1, 1);
        float npm2 = __shfl_down_sync(0xffffffffu, pm2, 1);
        float npm3 = __shfl_down_sync(0xffffffffu, pm3, 1);
        float nq0  = __shfl_down_sync(0xffffffffu, q0, 1);
        float nq1  = __shfl_down_sync(0xffffffffu, q1, 1);
        float nq2  = __shfl_down_sync(0xffffffffu, q2, 1);
        float nq3  = __shfl_down_sync(0xffffffffu, q3, 1);

        // Lane 31 takes its neighbor values from the exchange buffer.
        if (lane == 31) {
            const float4* xl = (const float4*)xbuf[buf][wrp];
            float4 a = xl[0], b = xl[1], c = xl[2];
            nmm0 = a.x; nmm1 = a.y; nmm2 = a.z; nmm3 = a.w;
            npm0 = b.x; npm1 = b.y; npm2 = b.z; npm3 = b.w;
            nq0  = c.x; nq1  = c.y; nq2  = c.z; nq3  = c.w;
        }

        // Sliding window-5 sums over {own0..3, n0..3}, incremental.
        float smm = mm0 + mm1 + mm2 + mm3 + nmm0;
        float spm = pm0 + pm1 + pm2 + pm3 + npm0;
        float sq  = q0 + q1 + q2 + q3 + nq0;
        WIN(0, acc0)
        smm += nmm1 - mm0; spm += npm1 - pm0; sq += nq1 - q0;
        WIN(1, acc1)
        smm += nmm2 - mm1; spm += npm2 - pm1; sq += nq2 - q1;
        WIN(2, acc2)
        smm += nmm3 - mm2; spm += npm3 - pm2; sq += nq3 - q2;
        WIN(3, acc3)

        fp4 += (LL / 2); t4p += (LL / 4); m4p += (LL / 4);
    }

    // Gate off windows >= NW (only the tail lane of the last block).
    unsigned amask = 0u;
    if (w + 0 < NW) amask |= 1u; else acc0 = 0.f;
    if (w + 1 < NW) amask |= 2u; else acc1 = 0.f;
    if (w + 2 < NW) amask |= 4u; else acc2 = 0.f;
    if (w + 3 < NW) amask |= 8u; else acc3 = 0.f;
    vmask &= amask;

    // Validity: ballot-pack, OR into global per-window bit array.
    // Integer atomicOr is order-independent -> deterministic.
    unsigned b0 = __ballot_sync(0xffffffffu, (vmask >> 0) & 1u);
    unsigned b1 = __ballot_sync(0xffffffffu, (vmask >> 1) & 1u);
    unsigned b2 = __ballot_sync(0xffffffffu, (vmask >> 2) & 1u);
    unsigned b3 = __ballot_sync(0xffffffffu, (vmask >> 3) & 1u);
    if (lane == 0) {
        const int wg = seg / SEGW;
        atomicOr(&g_vld_or[wg * 4 + 0], b0);
        atomicOr(&g_vld_or[wg * 4 + 1], b1);
        atomicOr(&g_vld_or[wg * 4 + 2], b2);
        atomicOr(&g_vld_or[wg * 4 + 3], b3);
        __threadfence();   // make this warp's ORs globally visible
    }

    // In-block deterministic reduction of sq -> one float per block.
    float a = (acc0 + acc1) + (acc2 + acc3);
    a += __shfl_xor_sync(0xffffffffu, a, 16);
    a += __shfl_xor_sync(0xffffffffu, a, 8);
    a += __shfl_xor_sync(0xffffffffu, a, 4);
    a += __shfl_xor_sync(0xffffffffu, a, 2);
    a += __shfl_xor_sync(0xffffffffu, a, 1);
    if (lane == 0) s_red[wrp] = a;
    __syncthreads();
    if (threadIdx.x == 0) {
        g_sq_blk[bch * NWCH + blockIdx.x] =
            (s_red[0] + s_red[1]) + (s_red[2] + s_red[3]);
        __threadfence();   // partial visible before arrival
        // Wrapping arrival counter: self-resets to 0 after NBLK increments.
        unsigned old = atomicInc(&g_done, NBLK - 1);
        s_last = (old == NBLK - 1) ? 1u : 0u;
    }
    __syncthreads();
    if (!s_last) return;

    // ---- Last block: final reduction (4 KB sq + 2 KB validity) ----
    __threadfence();       // acquire: all other blocks' fenced writes visible
    const int t = threadIdx.x;

    float s = 0.f;
    const float4* sq4 = (const float4*)g_sq_blk;   // 1024 floats = 256 float4
#pragma unroll
    for (int i = 0; i < 2; i++) {
        float4 v = sq4[t + 128 * i];
        s += (v.x + v.y) + (v.z + v.w);
    }
    uint4 vv = ((const uint4*)g_vld_or)[t];        // 512 words / 128 thr
    int c = __popc(vv.x) + __popc(vv.y) + __popc(vv.z) + __popc(vv.w);
    // Zero validity accumulator for the next graph replay.
    ((uint4*)g_vld_or)[t] = make_uint4(0u, 0u, 0u, 0u);

    // Block reduce s and c.
    s += __shfl_xor_sync(0xffffffffu, s, 16);
    s += __shfl_xor_sync(0xffffffffu, s, 8);
    s += __shfl_xor_sync(0xffffffffu, s, 4);
    s += __shfl_xor_sync(0xffffffffu, s, 2);
    s += __shfl_xor_sync(0xffffffffu, s, 1);
    c += __shfl_xor_sync(0xffffffffu, c, 16);
    c += __shfl_xor_sync(0xffffffffu, c, 8);
    c += __shfl_xor_sync(0xffffffffu, c, 4);
    c += __shfl_xor_sync(0xffffffffu, c, 2);
    c += __shfl_xor_sync(0xffffffffu, c, 1);
    __shared__ float fs[4];
    __shared__ int   fc[4];
    if (lane == 0) { fs[wrp] = s; fc[wrp] = c; }
    __syncthreads();
    if (t == 0) {
        float S = (fs[0] + fs[1]) + (fs[2] + fs[3]);
        int   C = (fc[0] + fc[1]) + (fc[2] + fc[3]);
        out[0] = S * (1.0f / (float)BB) / fmaxf((float)C, 1.0f);
    }
}

extern "C" void kernel_launch(void* const* d_in, const int* in_sizes, int n_in,
                              void* d_out, int out_size)
{
    const float* pred = (const float*)d_in[0];   // [512, 16384, 2] f32
    const int*   tgt  = (const int*)d_in[1];     // [512, 16384] i32
    const int*   msk  = (const int*)d_in[2];     // [512, 16384] i32

    dim3 grid(NWCH, NBCH);                        // 32 x 32 = 1024 blocks
    bcl_fused<<<grid, TPB>>>(pred, tgt, msk, (float*)d_out);
}